// round 14
// baseline (speedup 1.0000x reference)
#include <cuda_runtime.h>
#include <cuda_fp16.h>
#include <stdint.h>

#define BATCH   16
#define HID     256
#define HEADS   8
#define DH      32
#define NPIX    4096
#define QKV_ROWS 768
#define KP      256          // single-term fp16, K' = 256
#define NCHUNK  4            // K' / 64
#define CSEG    8            // context pixel segments

// ---------------- device scratch ------------------------------------------
__device__ __half g_ek[BATCH * 256 * NPIX];             // exp(k-4) fp16, 32 MB
__device__ __half g_v [BATCH * 256 * NPIX];             // v raw fp16, 32 MB
__device__ __half g_W2[QKV_ROWS * KP];                  // W fp16 [768,256]
__device__ __half g_Bx[BATCH * 4 * NPIX * 64];          // chunk-major x^T, 32 MB
__device__ __half g_Bq[BATCH * 4 * NPIX * 64];          // chunk-major softmaxed q^T, 32 MB
__device__ __half g_A2[BATCH * HID * KP];               // M fp16 [b,256,256]
__device__ float g_ctxp[BATCH * HEADS * CSEG * DH * DH]; // context partials
__device__ float g_kpart[BATCH * 256 * 32];             // k row sumexp partials per 128-col block

// ---------------- PTX helpers (base ISA only) ------------------------------
__device__ __forceinline__ uint32_t smem_u32(const void* p) {
    uint32_t a;
    asm("{ .reg .u64 t; cvta.to.shared.u64 t, %1; cvt.u32.u64 %0, t; }" : "=r"(a) : "l"(p));
    return a;
}
__device__ __forceinline__ void cp16(uint32_t saddr, const void* gaddr) {
    asm volatile("cp.async.cg.shared.global [%0], [%1], 16;" :: "r"(saddr), "l"(gaddr) : "memory");
}
__device__ __forceinline__ void cp_commit() {
    asm volatile("cp.async.commit_group;" ::: "memory");
}
template <int N>
__device__ __forceinline__ void cp_wait() {
    asm volatile("cp.async.wait_group %0;" :: "n"(N) : "memory");
}
__device__ __forceinline__ void ldsm_x4(uint32_t* r, uint32_t addr) {
    asm volatile("ldmatrix.sync.aligned.m8n8.x4.shared.b16 {%0,%1,%2,%3}, [%4];"
                 : "=r"(r[0]), "=r"(r[1]), "=r"(r[2]), "=r"(r[3]) : "r"(addr));
}
__device__ __forceinline__ void mma16816(float* c, const uint32_t* a, const uint32_t* b) {
    asm volatile(
        "mma.sync.aligned.m16n8k16.row.col.f32.f16.f16.f32 "
        "{%0,%1,%2,%3}, {%4,%5,%6,%7}, {%8,%9}, {%0,%1,%2,%3};"
        : "+f"(c[0]), "+f"(c[1]), "+f"(c[2]), "+f"(c[3])
        : "r"(a[0]), "r"(a[1]), "r"(a[2]), "r"(a[3]), "r"(b[0]), "r"(b[1]));
}

// 128B rows + XOR-16B swizzle: conflict-free ldmatrix across any 8-row phase
#define SW(row, col) (((uint32_t)(col)) ^ (((row) & 7) * 16))

#define LDS_B 128
#define OP1 (128 * LDS_B)        // 16384 per operand per stage
#define STG1 (2 * OP1)           // 32768 per stage
#define SMEM1 (3 * STG1)         // 98304, 3 stages

// ---------------------------------------------------------------------------
// GEMM1 + fused epilogues. 256 threads, 8 warps of 64x32, CTA 128x128, BK=64.
// bx 0-1: q (softmax -> g_Bq fp16); 2-3: k (exp(k-4) fp16 + row sums);
// 4-5: v (raw fp16).
// ---------------------------------------------------------------------------
__global__ __launch_bounds__(256, 2) void gemm_mma(
    const __half* __restrict__ A, const __half* __restrict__ B)
{
    extern __shared__ char smem[];
    const uint32_t sb = smem_u32(smem);
    const int tid = threadIdx.x;
    const int wid = tid >> 5;
    const int lane = tid & 31;
    const int bx = blockIdx.x, by = blockIdx.y, b = blockIdx.z;

    const char* Ab = (const char*)(A + (long)bx * 128 * KP);
    const char* Bb = (const char*)B + ((long)b * 4 * NPIX + (long)by * 128) * 128;

    const int wm = (wid >> 2) * 64;
    const int wn = (wid & 3) * 32;

    float acc[4][4][4];
    #pragma unroll
    for (int i = 0; i < 4; ++i)
        #pragma unroll
        for (int j = 0; j < 4; ++j)
            #pragma unroll
            for (int k = 0; k < 4; ++k) acc[i][j][k] = 0.f;

    const int r_ld = tid >> 3;              // 0..31
    const int c16 = (tid & 7) * 16;
    auto cp_chunk = [&](int c) {
        const uint32_t as = sb + (c % 3) * STG1;
        const uint32_t bs = as + OP1;
        const long akb = (long)c * 128;
        const long bko = (long)c * NPIX * 128;
        #pragma unroll
        for (int i = 0; i < 4; ++i) {
            const int r = r_ld + i * 32;
            const uint32_t so = r * LDS_B + SW(r, c16);
            cp16(as + so, Ab + (long)r * (KP * 2) + akb + c16);
            cp16(bs + so, Bb + bko + (long)r * 128 + c16);
        }
        cp_commit();
    };

    const int a_row = lane & 15;
    const int a_koff = (lane >> 4) * 16;
    const int swa = (a_row & 7) * 16;
    const int b_row = lane & 7;
    const int b_n8 = (lane >> 4) * 8;
    const int b_koff = ((lane >> 3) & 1) * 16;
    const int swb = b_row * 16;

    cp_chunk(0);
    cp_chunk(1);

    for (int c = 0; c < NCHUNK; ++c) {
        if (c < NCHUNK - 1) cp_wait<1>(); else cp_wait<0>();
        __syncthreads();
        if (c + 2 < NCHUNK) cp_chunk(c + 2);

        const uint32_t as = sb + (c % 3) * STG1;
        const uint32_t bs = as + OP1;
        #pragma unroll
        for (int ks = 0; ks < 4; ++ks) {
            uint32_t afr[4][4], bfr[4][2];
            #pragma unroll
            for (int mt = 0; mt < 4; ++mt)
                ldsm_x4(afr[mt], as + (wm + mt * 16 + a_row) * LDS_B + ((ks * 32 + a_koff) ^ swa));
            #pragma unroll
            for (int np = 0; np < 2; ++np) {
                uint32_t bq[4];
                ldsm_x4(bq, bs + (wn + np * 16 + b_n8 + b_row) * LDS_B + ((ks * 32 + b_koff) ^ swb));
                bfr[np * 2][0] = bq[0]; bfr[np * 2][1] = bq[1];
                bfr[np * 2 + 1][0] = bq[2]; bfr[np * 2 + 1][1] = bq[3];
            }
            #pragma unroll
            for (int mt = 0; mt < 4; ++mt)
                #pragma unroll
                for (int nt = 0; nt < 4; ++nt)
                    mma16816(acc[mt][nt], afr[mt], bfr[nt]);
        }
    }

    const int er = lane >> 2;
    const int ec = (lane & 3) * 2;

    if (bx >= 4) {
        // ---- v: raw fp16 ----------------------------------------------------
        __half* Vb = g_v + ((long)b * 256 + (long)(bx - 4) * 128) * 4096 + by * 128;
        #pragma unroll
        for (int mt = 0; mt < 4; ++mt)
            #pragma unroll
            for (int nt = 0; nt < 4; ++nt) {
                const long r0 = wm + mt * 16 + er;
                const int c0 = wn + nt * 8 + ec;
                *reinterpret_cast<__half2*>(Vb + r0 * 4096 + c0) =
                    __floats2half2_rn(acc[mt][nt][0], acc[mt][nt][1]);
                *reinterpret_cast<__half2*>(Vb + (r0 + 8) * 4096 + c0) =
                    __floats2half2_rn(acc[mt][nt][2], acc[mt][nt][3]);
            }
        return;
    }

    if (bx >= 2) {
        // ---- k: exp(k-4) fp16 + row-sum partials ---------------------------
        __half* Ek = g_ek + ((long)b * 256 + (long)(bx - 2) * 128) * 4096 + by * 128;
        float rs[8];
        #pragma unroll
        for (int i = 0; i < 8; ++i) rs[i] = 0.f;
        #pragma unroll
        for (int mt = 0; mt < 4; ++mt)
            #pragma unroll
            for (int nt = 0; nt < 4; ++nt) {
                const float e0 = __expf(acc[mt][nt][0] - 4.f);
                const float e1 = __expf(acc[mt][nt][1] - 4.f);
                const float e2 = __expf(acc[mt][nt][2] - 4.f);
                const float e3 = __expf(acc[mt][nt][3] - 4.f);
                const long r0 = wm + mt * 16 + er;
                const int c0 = wn + nt * 8 + ec;
                *reinterpret_cast<__half2*>(Ek + r0 * 4096 + c0) = __floats2half2_rn(e0, e1);
                *reinterpret_cast<__half2*>(Ek + (r0 + 8) * 4096 + c0) = __floats2half2_rn(e2, e3);
                rs[mt * 2] += e0 + e1;
                rs[mt * 2 + 1] += e2 + e3;
            }
        #pragma unroll
        for (int off = 1; off < 4; off <<= 1)
            #pragma unroll
            for (int i = 0; i < 8; ++i)
                rs[i] += __shfl_xor_sync(0xFFFFFFFFu, rs[i], off);

        float* ssum = (float*)smem;   // [128 rows][4 col-quarters]
        __syncthreads();
        if ((lane & 3) == 0) {
            const int wq = wid & 3;
            #pragma unroll
            for (int mt = 0; mt < 4; ++mt)
                #pragma unroll
                for (int h2 = 0; h2 < 2; ++h2)
                    ssum[(wm + mt * 16 + er + h2 * 8) * 4 + wq] = rs[mt * 2 + h2];
        }
        __syncthreads();
        if (tid < 128)
            g_kpart[((long)b * 256 + (bx - 2) * 128 + tid) * 32 + by] =
                ssum[tid * 4] + ssum[tid * 4 + 1] + ssum[tid * 4 + 2] + ssum[tid * 4 + 3];
        return;
    }

    // ---- q: stage to smem, softmax over d, emit fp16 chunk-major -----------
    float* sfl = (float*)smem;
    __syncthreads();
    #pragma unroll
    for (int mt = 0; mt < 4; ++mt)
        #pragma unroll
        for (int nt = 0; nt < 4; ++nt) {
            const int r0 = wm + mt * 16 + er;
            const int c0 = wn + nt * 8 + ec;
            sfl[r0 * 129 + c0] = acc[mt][nt][0];
            sfl[r0 * 129 + c0 + 1] = acc[mt][nt][1];
            sfl[(r0 + 8) * 129 + c0] = acc[mt][nt][2];
            sfl[(r0 + 8) * 129 + c0 + 1] = acc[mt][nt][3];
        }
    __syncthreads();

    #pragma unroll
    for (int t = tid; t < 512; t += 256) {
        const int hb = t >> 7;
        const int col = t & 127;
        float v[DH];
        float m = -1e30f;
        #pragma unroll
        for (int d = 0; d < DH; ++d) {
            v[d] = sfl[(hb * 32 + d) * 129 + col];
            m = fmaxf(m, v[d]);
        }
        float s = 0.f;
        #pragma unroll
        for (int d = 0; d < DH; ++d) { v[d] = __expf(v[d] - m); s += v[d]; }
        const float inv = 0.1767766952966369f / s;
        __align__(16) __half o[DH];
        #pragma unroll
        for (int d = 0; d < DH; ++d) o[d] = __float2half(v[d] * inv);

        const int gh = bx * 4 + hb;
        const long gcol = (long)by * 128 + col;
        __half* ob = g_Bq + (((long)b * 4 + (gh >> 1)) * NPIX + gcol) * 64 + (gh & 1) * 32;
        #pragma unroll
        for (int i = 0; i < 4; ++i)
            reinterpret_cast<uint4*>(ob)[i] = reinterpret_cast<const uint4*>(o)[i];
    }
}

// ---------------------------------------------------------------------------
// GEMM2 + fused bias + LayerNorm. CTA tile 256x64, 256 threads, 2 CTAs/SM.
// 2-stage cp.async, ONE sync per chunk (cp issued after the leading barrier).
// ---------------------------------------------------------------------------
#define A2_ST (256 * LDS_B)       // 32768
#define B2_ST (64 * LDS_B)        // 8192
#define STG2  (A2_ST + B2_ST)     // 40960 per stage

__global__ __launch_bounds__(256, 2) void gemm_ln(
    const __half* __restrict__ A, const __half* __restrict__ B,
    const float* __restrict__ bout, const float* __restrict__ gam,
    float* __restrict__ out)
{
    extern __shared__ char smem[];
    const uint32_t sb = smem_u32(smem);
    const int tid = threadIdx.x;
    const int wid = tid >> 5;
    const int lane = tid & 31;
    const int b = blockIdx.z;
    const int n0 = blockIdx.x * 64;

    const char* Ab = (const char*)(A + (long)b * HID * KP);
    const char* Bb = (const char*)B + ((long)b * 4 * NPIX + n0) * 128;
    float* Cb = out + (long)b * HID * NPIX + n0;

    const int wm = (wid >> 1) * 64;
    const int wn = (wid & 1) * 32;

    float acc[4][4][4];
    #pragma unroll
    for (int i = 0; i < 4; ++i)
        #pragma unroll
        for (int j = 0; j < 4; ++j)
            #pragma unroll
            for (int k = 0; k < 4; ++k) acc[i][j][k] = 0.f;

    const int r_ld = tid >> 3;
    const int c16 = (tid & 7) * 16;
    auto cp_chunk = [&](int c, int s) {
        const uint32_t as = sb + s * STG2;
        const uint32_t bs = as + A2_ST;
        const long akb = (long)c * 128;
        const long bko = (long)c * NPIX * 128;
        #pragma unroll
        for (int i = 0; i < 8; ++i) {
            const int r = r_ld + i * 32;
            cp16(as + r * LDS_B + SW(r, c16), Ab + (long)r * (KP * 2) + akb + c16);
        }
        #pragma unroll
        for (int i = 0; i < 2; ++i) {
            const int r = r_ld + i * 32;
            cp16(bs + r * LDS_B + SW(r, c16), Bb + bko + (long)r * 128 + c16);
        }
        cp_commit();
    };

    const int a_row = lane & 15;
    const int a_koff = (lane >> 4) * 16;
    const int swa = (a_row & 7) * 16;
    const int b_row = lane & 7;
    const int b_n8 = (lane >> 4) * 8;
    const int b_koff = ((lane >> 3) & 1) * 16;
    const int swb = b_row * 16;

    cp_chunk(0, 0);

    #pragma unroll
    for (int c = 0; c < NCHUNK; ++c) {
        const int s = c & 1;
        cp_wait<0>();
        __syncthreads();
        if (c + 1 < NCHUNK) cp_chunk(c + 1, s ^ 1);

        const uint32_t as = sb + s * STG2;
        const uint32_t bs = as + A2_ST;
        #pragma unroll
        for (int ks = 0; ks < 4; ++ks) {
            uint32_t afr[4][4], bfr[4][2];
            #pragma unroll
            for (int mt = 0; mt < 4; ++mt)
                ldsm_x4(afr[mt], as + (wm + mt * 16 + a_row) * LDS_B + ((ks * 32 + a_koff) ^ swa));
            #pragma unroll
            for (int np = 0; np < 2; ++np) {
                uint32_t bq[4];
                ldsm_x4(bq, bs + (wn + np * 16 + b_n8 + b_row) * LDS_B + ((ks * 32 + b_koff) ^ swb));
                bfr[np * 2][0] = bq[0]; bfr[np * 2][1] = bq[1];
                bfr[np * 2 + 1][0] = bq[2]; bfr[np * 2 + 1][1] = bq[3];
            }
            #pragma unroll
            for (int mt = 0; mt < 4; ++mt)
                #pragma unroll
                for (int nt = 0; nt < 4; ++nt)
                    mma16816(acc[mt][nt], afr[mt], bfr[nt]);
        }
    }

    const int er = lane >> 2;
    const int ec = (lane & 3) * 2;

    float bo[8], ga[8];
    #pragma unroll
    for (int mt = 0; mt < 4; ++mt) {
        const int r0 = wm + mt * 16 + er;
        bo[mt * 2] = bout[r0];        bo[mt * 2 + 1] = bout[r0 + 8];
        ga[mt * 2] = gam[r0];         ga[mt * 2 + 1] = gam[r0 + 8];
    }

    float cs[4][2], cq[4][2];
    #pragma unroll
    for (int nt = 0; nt < 4; ++nt)
        #pragma unroll
        for (int par = 0; par < 2; ++par) {
            float s = 0.f, q = 0.f;
            #pragma unroll
            for (int mt = 0; mt < 4; ++mt) {
                float v0 = acc[mt][nt][par]     + bo[mt * 2];
                float v1 = acc[mt][nt][par + 2] + bo[mt * 2 + 1];
                acc[mt][nt][par] = v0;
                acc[mt][nt][par + 2] = v1;
                s += v0 + v1;
                q += v0 * v0 + v1 * v1;
            }
            cs[nt][par] = s;
            cq[nt][par] = q;
        }
    #pragma unroll
    for (int off = 4; off < 32; off <<= 1)
        #pragma unroll
        for (int nt = 0; nt < 4; ++nt)
            #pragma unroll
            for (int par = 0; par < 2; ++par) {
                cs[nt][par] += __shfl_xor_sync(0xFFFFFFFFu, cs[nt][par], off);
                cq[nt][par] += __shfl_xor_sync(0xFFFFFFFFu, cq[nt][par], off);
            }

    float* red = (float*)smem;
    float2* lnp = (float2*)(smem + 2048);
    __syncthreads();
    if (er == 0) {
        const int wr = wid >> 1;
        #pragma unroll
        for (int nt = 0; nt < 4; ++nt)
            #pragma unroll
            for (int par = 0; par < 2; ++par) {
                const int col = wn + nt * 8 + ec + par;
                red[(wr * 64 + col) * 2]     = cs[nt][par];
                red[(wr * 64 + col) * 2 + 1] = cq[nt][par];
            }
    }
    __syncthreads();
    if (tid < 64) {
        float s = 0.f, q = 0.f;
        #pragma unroll
        for (int wr = 0; wr < 4; ++wr) {
            s += red[(wr * 64 + tid) * 2];
            q += red[(wr * 64 + tid) * 2 + 1];
        }
        const float mean = s * (1.f / 256.f);
        const float var = q * (1.f / 256.f) - mean * mean;
        lnp[tid] = make_float2(mean, rsqrtf(var + 1e-5f));
    }
    __syncthreads();

    #pragma unroll
    for (int mt = 0; mt < 4; ++mt)
        #pragma unroll
        for (int nt = 0; nt < 4; ++nt) {
            const float2 l0 = lnp[wn + nt * 8 + ec];
            const float2 l1 = lnp[wn + nt * 8 + ec + 1];
            float* p0 = Cb + (long)(wm + mt * 16 + er) * 4096 + wn + nt * 8 + ec;
            *reinterpret_cast<float2*>(p0) = make_float2(
                (acc[mt][nt][0] - l0.x) * l0.y * ga[mt * 2],
                (acc[mt][nt][1] - l1.x) * l1.y * ga[mt * 2]);
            *reinterpret_cast<float2*>(p0 + 8L * 4096) = make_float2(
                (acc[mt][nt][2] - l0.x) * l0.y * ga[mt * 2 + 1],
                (acc[mt][nt][3] - l1.x) * l1.y * ga[mt * 2 + 1]);
        }
}

// ---------------------------------------------------------------------------
__global__ __launch_bounds__(256) void conv_w_kernel(const float* __restrict__ w)
{
    const int m = blockIdx.x, c = threadIdx.x;
    g_W2[(long)m * KP + c] = __float2half(w[m * 256 + c]);
}

// ---------------------------------------------------------------------------
// x transpose: 64c x 128p tiles, float4 loads (MLP 8), 128B pixel-row writes.
// ---------------------------------------------------------------------------
__global__ __launch_bounds__(256) void transpose_x(const float* __restrict__ x, int zoff)
{
    __shared__ float sm[64][129];
    const int b = blockIdx.z + zoff, c0 = blockIdx.y * 64, p0 = blockIdx.x * 128;
    const float* xb = x + ((long)b * 256 + c0) * 4096 + p0;
    const int tid = threadIdx.x;

    #pragma unroll
    for (int i = 0; i < 8; ++i) {
        const int u = tid + i * 256;        // 0..2047 float4 slots
        const int r = u >> 5;               // 0..63
        const int c4 = (u & 31) * 4;        // 0..124
        const float4 v = *reinterpret_cast<const float4*>(xb + (long)r * 4096 + c4);
        sm[r][c4] = v.x; sm[r][c4 + 1] = v.y; sm[r][c4 + 2] = v.z; sm[r][c4 + 3] = v.w;
    }
    __syncthreads();

    const int p = tid >> 1;                 // pixel 0..127
    const int ch0 = (tid & 1) * 32;         // channel half
    __align__(16) __half hv[32];
    #pragma unroll
    for (int j = 0; j < 32; ++j) hv[j] = __float2half(sm[ch0 + j][p]);

    __half* ob = g_Bx + (((long)b * 4 + blockIdx.y) * NPIX + p0 + p) * 64 + ch0;
    #pragma unroll
    for (int i = 0; i < 4; ++i)
        reinterpret_cast<uint4*>(ob)[i] = reinterpret_cast<const uint4*>(hv)[i];
}

// ---------------------------------------------------------------------------
// context via tensor cores: ctx[32,32] = ek[32,K] * v[32,K]^T per (b,h).
// grid (128 bh, 8 segs), 128 threads / 4 warps; swizzled 128B smem rows.
// ---------------------------------------------------------------------------
__global__ __launch_bounds__(128) void context_mma()
{
    __shared__ __half sK[3][DH][64];
    __shared__ __half sV[3][DH][64];
    __shared__ float red[4][DH][DH + 1];
    __shared__ float ki[DH];

    const int bh = blockIdx.x, seg = blockIdx.y;
    const int b = bh >> 3, h = bh & 7;
    const __half* kb = g_ek + ((long)b * 256 + h * DH) * 4096 + seg * 512;
    const __half* vb = g_v  + ((long)b * 256 + h * DH) * 4096 + seg * 512;

    const int tid = threadIdx.x;
    const int wid = tid >> 5;
    const int lane = tid & 31;

    if (tid < DH) {
        const float* pp = g_kpart + ((long)b * 256 + h * DH + tid) * 32;
        float s = 0.f;
        #pragma unroll
        for (int i = 0; i < 32; ++i) s += pp[i];
        ki[tid] = 1.f / s;
    }

    auto cp_stage = [&](int it) {
        const int s = it % 3;
        const int p0 = it * 64;
        const uint32_t aK = smem_u32(&sK[s][0][0]);
        const uint32_t aV = smem_u32(&sV[s][0][0]);
        #pragma unroll
        for (int i = 0; i < 2; ++i) {
            const int u = tid + i * 128;            // 0..255
            const int row = u >> 3;
            const uint32_t so = row * 128 + SW(row, (u & 7) * 16);
            cp16(aK + so, kb + (long)row * 4096 + p0 + (u & 7) * 8);
            cp16(aV + so, vb + (long)row * 4096 + p0 + (u & 7) * 8);
        }
        cp_commit();
    };

    float acc[2][4][4];
    #pragma unroll
    for (int i = 0; i < 2; ++i)
        #pragma unroll
        for (int j = 0; j < 4; ++j)
            #pragma unroll
            for (int k = 0; k < 4; ++k) acc[i][j][k] = 0.f;

    const int a_row = lane & 15;
    const int a_koff = (lane >> 4) * 16;
    const int swa = (a_row & 7) * 16;
    const int b_row = lane & 7;
    const int b_n8 = (lane >> 4) * 8;
    const int b_koff = ((lane >> 3) & 1) * 16;
    const int swb = b_row * 16;
    const int kwb = wid * 32;                       // warp k-slice byte offset

    cp_stage(0);
    cp_stage(1);

    for (int it = 0; it < 8; ++it) {
        const int s = it % 3;
        if (it < 7) cp_wait<1>(); else cp_wait<0>();
        __syncthreads();
        if (it + 2 < 8) cp_stage(it + 2);

        const uint32_t aK = smem_u32(&sK[s][0][0]);
        const uint32_t aV = smem_u32(&sV[s][0][0]);
        uint32_t afr[2][4], bfr[4][2];
        #pragma unroll
        for (int mt = 0; mt < 2; ++mt)
            ldsm_x4(afr[mt], aK + (mt * 16 + a_row) * 128 + ((kwb + a_koff) ^ swa));
        #pragma unroll
        for (int np = 0; np < 2; ++np) {
            uint32_t bq[4];
            ldsm_x4(bq, aV + (np * 16 + b_n8 + b_row) * 128 + ((kwb + b_koff) ^ swb));
            bfr[np * 2][0] = bq[0]; bfr[np * 2][1] = bq[1];
            bfr[np * 2 + 1][0] = bq[2]; bfr[np * 2 + 1][1] = bq[3];
        }
        #pragma unroll
        for (int mt = 0; mt < 2; ++mt)
            #pragma unroll
            for (int nt = 0; nt < 4; ++nt)
                mma16816(acc[mt][nt], afr[mt], bfr[nt]);
    }

    // ---- cross-warp reduce + ki scaling -------------------------------------
    const int er = lane >> 2;
    const int ec = (lane & 3) * 2;
    #pragma unroll
    for (int mt = 0; mt < 2; ++mt)
        #pragma unroll
        for (int nt = 0; nt < 4; ++nt) {
            const int d0 = mt * 16 + er;
            const int e0 = nt * 8 + ec;
            red[wid][d0][e0]     = acc[mt][nt][0];
            red[wid][d0][e0 + 1] = acc[mt][nt][1];
            red[wid][d0 + 8][e0]     = acc[mt][nt][2];
            red[wid][d0 + 8][e0 + 1] = acc[mt][nt][3];
        }
    __syncthreads();

    float* op = g_ctxp + ((long)bh * CSEG + seg) * (DH * DH);
    const float invn = 1.f / (float)NPIX;
    #pragma unroll
    for (int i = tid; i < DH * DH; i += 128) {
        const int d = i >> 5, e = i & 31;
        const float s = red[0][d][e] + red[1][d][e] + red[2][d][e] + red[3][d][e];
        op[i] = s * ki[d] * invn;
    }
}

// ---------------------------------------------------------------------------
// buildM -> single fp16 M in g_A2
// ---------------------------------------------------------------------------
__global__ __launch_bounds__(256) void buildM_kernel(const float* __restrict__ wout)
{
    const int bh = blockIdx.x;
    const int b = bh >> 3, h = bh & 7;

    __shared__ float cs[DH][DH + 1];
    const int tid = threadIdx.x;

    for (int i = tid; i < DH * DH; i += 256) {
        float s = 0.f;
        #pragma unroll
        for (int ch = 0; ch < CSEG; ++ch)
            s += g_ctxp[((long)bh * CSEG + ch) * (DH * DH) + i];
        cs[i >> 5][i & 31] = s;
    }
    __syncthreads();

    float w[DH];
    const float* wr = wout + (long)tid * 256 + h * DH;
    #pragma unroll
    for (int e = 0; e < DH; ++e) w[e] = wr[e];

    __align__(16) __half hi[DH];
    for (int d = 0; d < DH; ++d) {
        float s = 0.f;
        #pragma unroll
        for (int e = 0; e < DH; ++e) s += w[e] * cs[d][e];
        hi[d] = __float2half(s);
    }
    __half* ob = g_A2 + ((long)b * HID + tid) * KP + h * DH;
    #pragma unroll
    for (int i = 0; i < 4; ++i)
        reinterpret_cast<uint4*>(ob)[i] = reinterpret_cast<const uint4*>(hi)[i];
}

// ---------------------------------------------------------------------------
extern "C" void kernel_launch(void* const* d_in, const int* in_sizes, int n_in,
                              void* d_out, int out_size)
{
    (void)in_sizes; (void)n_in; (void)out_size;
    const float* x     = (const float*)d_in[0];
    const float* w_qkv = (const float*)d_in[1];
    const float* w_out = (const float*)d_in[2];
    const float* b_out = (const float*)d_in[3];
    const float* g     = (const float*)d_in[4];
    float* out = (float*)d_out;

    __half *p_W = nullptr, *p_Bx = nullptr, *p_Bq = nullptr, *p_A2 = nullptr;
    cudaGetSymbolAddress((void**)&p_W,   g_W2);
    cudaGetSymbolAddress((void**)&p_Bx,  g_Bx);
    cudaGetSymbolAddress((void**)&p_Bq,  g_Bq);
    cudaGetSymbolAddress((void**)&p_A2,  g_A2);

    cudaFuncSetAttribute(gemm_mma, cudaFuncAttributeMaxDynamicSharedMemorySize, SMEM1);
    cudaFuncSetAttribute(gemm_ln,  cudaFuncAttributeMaxDynamicSharedMemorySize, 2 * STG2);

    // slots 0-2 (keeps gemm_mma at ncu slot 3)
    conv_w_kernel<<<QKV_ROWS, 256>>>(w_qkv);
    transpose_x<<<dim3(32, 4, 8), 256>>>(x, 0);
    transpose_x<<<dim3(32, 4, 8), 256>>>(x, 8);

    // slot 3: QKV GEMM (single fp16, K=256, swizzled smem) + fused epilogues
    gemm_mma<<<dim3(6, 32, BATCH), 256, SMEM1>>>(p_W, p_Bx);

    // context partials via tensor cores (8 segments)
    context_mma<<<dim3(BATCH * HEADS, CSEG), 128>>>();

    // M fold -> single fp16
    buildM_kernel<<<BATCH * HEADS, 256>>>(w_out);

    // y GEMM (256x64 tiles, 256 thr, 2 CTAs/SM, 1-sync loop) + bias + LN
    gemm_ln<<<dim3(64, 1, BATCH), 256, 2 * STG2>>>(p_A2, p_Bq, b_out, g, out);
}

// round 15
// speedup vs baseline: 1.0448x; 1.0448x over previous
#include <cuda_runtime.h>
#include <cuda_fp16.h>
#include <stdint.h>

#define BATCH   16
#define HID     256
#define HEADS   8
#define DH      32
#define NPIX    4096
#define QKV_ROWS 768
#define KP      256          // single-term fp16, K' = 256
#define NCHUNK  4            // K' / 64
#define CSEG    8            // context pixel segments

// ---------------- device scratch ------------------------------------------
__device__ __half g_ek[BATCH * 256 * NPIX];             // exp(k-4) fp16, 32 MB
__device__ __half g_v [BATCH * 256 * NPIX];             // v raw fp16, 32 MB
__device__ __half g_W2[QKV_ROWS * KP];                  // W fp16 [768,256]
__device__ __half g_Bx[BATCH * 4 * NPIX * 64];          // chunk-major x^T, 32 MB
__device__ __half g_Bq[BATCH * 4 * NPIX * 64];          // chunk-major softmaxed q^T, 32 MB
__device__ __half g_A2[BATCH * HID * KP];               // M fp16 [b,256,256]
__device__ float g_ctxp[BATCH * HEADS * CSEG * DH * DH]; // context partials
__device__ float g_kpart[BATCH * 256 * 32];             // k row sumexp partials per 128-col block

// ---------------- PTX helpers (base ISA only) ------------------------------
__device__ __forceinline__ uint32_t smem_u32(const void* p) {
    uint32_t a;
    asm("{ .reg .u64 t; cvta.to.shared.u64 t, %1; cvt.u32.u64 %0, t; }" : "=r"(a) : "l"(p));
    return a;
}
__device__ __forceinline__ void cp16(uint32_t saddr, const void* gaddr) {
    asm volatile("cp.async.cg.shared.global [%0], [%1], 16;" :: "r"(saddr), "l"(gaddr) : "memory");
}
__device__ __forceinline__ void cp_commit() {
    asm volatile("cp.async.commit_group;" ::: "memory");
}
template <int N>
__device__ __forceinline__ void cp_wait() {
    asm volatile("cp.async.wait_group %0;" :: "n"(N) : "memory");
}
__device__ __forceinline__ void ldsm_x4(uint32_t* r, uint32_t addr) {
    asm volatile("ldmatrix.sync.aligned.m8n8.x4.shared.b16 {%0,%1,%2,%3}, [%4];"
                 : "=r"(r[0]), "=r"(r[1]), "=r"(r[2]), "=r"(r[3]) : "r"(addr));
}
__device__ __forceinline__ void mma16816(float* c, const uint32_t* a, const uint32_t* b) {
    asm volatile(
        "mma.sync.aligned.m16n8k16.row.col.f32.f16.f16.f32 "
        "{%0,%1,%2,%3}, {%4,%5,%6,%7}, {%8,%9}, {%0,%1,%2,%3};"
        : "+f"(c[0]), "+f"(c[1]), "+f"(c[2]), "+f"(c[3])
        : "r"(a[0]), "r"(a[1]), "r"(a[2]), "r"(a[3]), "r"(b[0]), "r"(b[1]));
}

// 128B rows + XOR-16B swizzle: conflict-free ldmatrix across any 8-row phase
#define SW(row, col) (((uint32_t)(col)) ^ (((row) & 7) * 16))

#define LDS_B 128
#define OP1 (128 * LDS_B)        // 16384 per operand per stage
#define STG1 (2 * OP1)           // 32768 per stage
#define SMEM1 (3 * STG1)         // 98304, 3 stages

// ---------------------------------------------------------------------------
// GEMM1 + fused epilogues. 256 threads, 8 warps of 64x32, CTA 128x128, BK=64.
// bx 0-1: q (softmax -> g_Bq fp16); 2-3: k (exp(k-4) fp16 + row sums);
// 4-5: v (raw fp16).
// ---------------------------------------------------------------------------
__global__ __launch_bounds__(256, 2) void gemm_mma(
    const __half* __restrict__ A, const __half* __restrict__ B)
{
    extern __shared__ char smem[];
    const uint32_t sb = smem_u32(smem);
    const int tid = threadIdx.x;
    const int wid = tid >> 5;
    const int lane = tid & 31;
    const int bx = blockIdx.x, by = blockIdx.y, b = blockIdx.z;

    const char* Ab = (const char*)(A + (long)bx * 128 * KP);
    const char* Bb = (const char*)B + ((long)b * 4 * NPIX + (long)by * 128) * 128;

    const int wm = (wid >> 2) * 64;
    const int wn = (wid & 3) * 32;

    float acc[4][4][4];
    #pragma unroll
    for (int i = 0; i < 4; ++i)
        #pragma unroll
        for (int j = 0; j < 4; ++j)
            #pragma unroll
            for (int k = 0; k < 4; ++k) acc[i][j][k] = 0.f;

    const int r_ld = tid >> 3;              // 0..31
    const int c16 = (tid & 7) * 16;
    auto cp_chunk = [&](int c) {
        const uint32_t as = sb + (c % 3) * STG1;
        const uint32_t bs = as + OP1;
        const long akb = (long)c * 128;
        const long bko = (long)c * NPIX * 128;
        #pragma unroll
        for (int i = 0; i < 4; ++i) {
            const int r = r_ld + i * 32;
            const uint32_t so = r * LDS_B + SW(r, c16);
            cp16(as + so, Ab + (long)r * (KP * 2) + akb + c16);
            cp16(bs + so, Bb + bko + (long)r * 128 + c16);
        }
        cp_commit();
    };

    const int a_row = lane & 15;
    const int a_koff = (lane >> 4) * 16;
    const int swa = (a_row & 7) * 16;
    const int b_row = lane & 7;
    const int b_n8 = (lane >> 4) * 8;
    const int b_koff = ((lane >> 3) & 1) * 16;
    const int swb = b_row * 16;

    cp_chunk(0);
    cp_chunk(1);

    for (int c = 0; c < NCHUNK; ++c) {
        if (c < NCHUNK - 1) cp_wait<1>(); else cp_wait<0>();
        __syncthreads();
        if (c + 2 < NCHUNK) cp_chunk(c + 2);

        const uint32_t as = sb + (c % 3) * STG1;
        const uint32_t bs = as + OP1;
        #pragma unroll
        for (int ks = 0; ks < 4; ++ks) {
            uint32_t afr[4][4], bfr[4][2];
            #pragma unroll
            for (int mt = 0; mt < 4; ++mt)
                ldsm_x4(afr[mt], as + (wm + mt * 16 + a_row) * LDS_B + ((ks * 32 + a_koff) ^ swa));
            #pragma unroll
            for (int np = 0; np < 2; ++np) {
                uint32_t bq[4];
                ldsm_x4(bq, bs + (wn + np * 16 + b_n8 + b_row) * LDS_B + ((ks * 32 + b_koff) ^ swb));
                bfr[np * 2][0] = bq[0]; bfr[np * 2][1] = bq[1];
                bfr[np * 2 + 1][0] = bq[2]; bfr[np * 2 + 1][1] = bq[3];
            }
            #pragma unroll
            for (int mt = 0; mt < 4; ++mt)
                #pragma unroll
                for (int nt = 0; nt < 4; ++nt)
                    mma16816(acc[mt][nt], afr[mt], bfr[nt]);
        }
    }

    const int er = lane >> 2;
    const int ec = (lane & 3) * 2;

    if (bx >= 4) {
        // ---- v: raw fp16 ----------------------------------------------------
        __half* Vb = g_v + ((long)b * 256 + (long)(bx - 4) * 128) * 4096 + by * 128;
        #pragma unroll
        for (int mt = 0; mt < 4; ++mt)
            #pragma unroll
            for (int nt = 0; nt < 4; ++nt) {
                const long r0 = wm + mt * 16 + er;
                const int c0 = wn + nt * 8 + ec;
                *reinterpret_cast<__half2*>(Vb + r0 * 4096 + c0) =
                    __floats2half2_rn(acc[mt][nt][0], acc[mt][nt][1]);
                *reinterpret_cast<__half2*>(Vb + (r0 + 8) * 4096 + c0) =
                    __floats2half2_rn(acc[mt][nt][2], acc[mt][nt][3]);
            }
        return;
    }

    if (bx >= 2) {
        // ---- k: exp(k-4) fp16 + row-sum partials ---------------------------
        __half* Ek = g_ek + ((long)b * 256 + (long)(bx - 2) * 128) * 4096 + by * 128;
        float rs[8];
        #pragma unroll
        for (int i = 0; i < 8; ++i) rs[i] = 0.f;
        #pragma unroll
        for (int mt = 0; mt < 4; ++mt)
            #pragma unroll
            for (int nt = 0; nt < 4; ++nt) {
                const float e0 = __expf(acc[mt][nt][0] - 4.f);
                const float e1 = __expf(acc[mt][nt][1] - 4.f);
                const float e2 = __expf(acc[mt][nt][2] - 4.f);
                const float e3 = __expf(acc[mt][nt][3] - 4.f);
                const long r0 = wm + mt * 16 + er;
                const int c0 = wn + nt * 8 + ec;
                *reinterpret_cast<__half2*>(Ek + r0 * 4096 + c0) = __floats2half2_rn(e0, e1);
                *reinterpret_cast<__half2*>(Ek + (r0 + 8) * 4096 + c0) = __floats2half2_rn(e2, e3);
                rs[mt * 2] += e0 + e1;
                rs[mt * 2 + 1] += e2 + e3;
            }
        #pragma unroll
        for (int off = 1; off < 4; off <<= 1)
            #pragma unroll
            for (int i = 0; i < 8; ++i)
                rs[i] += __shfl_xor_sync(0xFFFFFFFFu, rs[i], off);

        float* ssum = (float*)smem;   // [128 rows][4 col-quarters]
        __syncthreads();
        if ((lane & 3) == 0) {
            const int wq = wid & 3;
            #pragma unroll
            for (int mt = 0; mt < 4; ++mt)
                #pragma unroll
                for (int h2 = 0; h2 < 2; ++h2)
                    ssum[(wm + mt * 16 + er + h2 * 8) * 4 + wq] = rs[mt * 2 + h2];
        }
        __syncthreads();
        if (tid < 128)
            g_kpart[((long)b * 256 + (bx - 2) * 128 + tid) * 32 + by] =
                ssum[tid * 4] + ssum[tid * 4 + 1] + ssum[tid * 4 + 2] + ssum[tid * 4 + 3];
        return;
    }

    // ---- q: stage to smem, softmax over d, emit fp16 chunk-major -----------
    float* sfl = (float*)smem;
    __syncthreads();
    #pragma unroll
    for (int mt = 0; mt < 4; ++mt)
        #pragma unroll
        for (int nt = 0; nt < 4; ++nt) {
            const int r0 = wm + mt * 16 + er;
            const int c0 = wn + nt * 8 + ec;
            sfl[r0 * 129 + c0] = acc[mt][nt][0];
            sfl[r0 * 129 + c0 + 1] = acc[mt][nt][1];
            sfl[(r0 + 8) * 129 + c0] = acc[mt][nt][2];
            sfl[(r0 + 8) * 129 + c0 + 1] = acc[mt][nt][3];
        }
    __syncthreads();

    #pragma unroll
    for (int t = tid; t < 512; t += 256) {
        const int hb = t >> 7;
        const int col = t & 127;
        float v[DH];
        float m = -1e30f;
        #pragma unroll
        for (int d = 0; d < DH; ++d) {
            v[d] = sfl[(hb * 32 + d) * 129 + col];
            m = fmaxf(m, v[d]);
        }
        float s = 0.f;
        #pragma unroll
        for (int d = 0; d < DH; ++d) { v[d] = __expf(v[d] - m); s += v[d]; }
        const float inv = 0.1767766952966369f / s;
        __align__(16) __half o[DH];
        #pragma unroll
        for (int d = 0; d < DH; ++d) o[d] = __float2half(v[d] * inv);

        const int gh = bx * 4 + hb;
        const long gcol = (long)by * 128 + col;
        __half* ob = g_Bq + (((long)b * 4 + (gh >> 1)) * NPIX + gcol) * 64 + (gh & 1) * 32;
        #pragma unroll
        for (int i = 0; i < 4; ++i)
            reinterpret_cast<uint4*>(ob)[i] = reinterpret_cast<const uint4*>(o)[i];
    }
}

// ---------------------------------------------------------------------------
// GEMM2 + fused bias + LayerNorm. CTA tile 256x64, 256 threads, 2 CTAs/SM.
// ---------------------------------------------------------------------------
#define A2_ST (256 * LDS_B)       // 32768
#define B2_ST (64 * LDS_B)        // 8192
#define STG2  (A2_ST + B2_ST)     // 40960 per stage

__global__ __launch_bounds__(256, 2) void gemm_ln(
    const __half* __restrict__ A, const __half* __restrict__ B,
    const float* __restrict__ bout, const float* __restrict__ gam,
    float* __restrict__ out)
{
    extern __shared__ char smem[];
    const uint32_t sb = smem_u32(smem);
    const int tid = threadIdx.x;
    const int wid = tid >> 5;
    const int lane = tid & 31;
    const int b = blockIdx.z;
    const int n0 = blockIdx.x * 64;

    const char* Ab = (const char*)(A + (long)b * HID * KP);
    const char* Bb = (const char*)B + ((long)b * 4 * NPIX + n0) * 128;
    float* Cb = out + (long)b * HID * NPIX + n0;

    const int wm = (wid >> 1) * 64;
    const int wn = (wid & 1) * 32;

    float acc[4][4][4];
    #pragma unroll
    for (int i = 0; i < 4; ++i)
        #pragma unroll
        for (int j = 0; j < 4; ++j)
            #pragma unroll
            for (int k = 0; k < 4; ++k) acc[i][j][k] = 0.f;

    const int r_ld = tid >> 3;
    const int c16 = (tid & 7) * 16;
    auto cp_chunk = [&](int c, int s) {
        const uint32_t as = sb + s * STG2;
        const uint32_t bs = as + A2_ST;
        const long akb = (long)c * 128;
        const long bko = (long)c * NPIX * 128;
        #pragma unroll
        for (int i = 0; i < 8; ++i) {
            const int r = r_ld + i * 32;
            cp16(as + r * LDS_B + SW(r, c16), Ab + (long)r * (KP * 2) + akb + c16);
        }
        #pragma unroll
        for (int i = 0; i < 2; ++i) {
            const int r = r_ld + i * 32;
            cp16(bs + r * LDS_B + SW(r, c16), Bb + bko + (long)r * 128 + c16);
        }
        cp_commit();
    };

    const int a_row = lane & 15;
    const int a_koff = (lane >> 4) * 16;
    const int swa = (a_row & 7) * 16;
    const int b_row = lane & 7;
    const int b_n8 = (lane >> 4) * 8;
    const int b_koff = ((lane >> 3) & 1) * 16;
    const int swb = b_row * 16;

    cp_chunk(0, 0);

    #pragma unroll
    for (int c = 0; c < NCHUNK; ++c) {
        const int s = c & 1;
        if (c + 1 < NCHUNK) cp_chunk(c + 1, s ^ 1);
        if (c + 1 < NCHUNK) cp_wait<1>(); else cp_wait<0>();
        __syncthreads();

        const uint32_t as = sb + s * STG2;
        const uint32_t bs = as + A2_ST;
        #pragma unroll
        for (int ks = 0; ks < 4; ++ks) {
            uint32_t afr[4][4], bfr[4][2];
            #pragma unroll
            for (int mt = 0; mt < 4; ++mt)
                ldsm_x4(afr[mt], as + (wm + mt * 16 + a_row) * LDS_B + ((ks * 32 + a_koff) ^ swa));
            #pragma unroll
            for (int np = 0; np < 2; ++np) {
                uint32_t bq[4];
                ldsm_x4(bq, bs + (wn + np * 16 + b_n8 + b_row) * LDS_B + ((ks * 32 + b_koff) ^ swb));
                bfr[np * 2][0] = bq[0]; bfr[np * 2][1] = bq[1];
                bfr[np * 2 + 1][0] = bq[2]; bfr[np * 2 + 1][1] = bq[3];
            }
            #pragma unroll
            for (int mt = 0; mt < 4; ++mt)
                #pragma unroll
                for (int nt = 0; nt < 4; ++nt)
                    mma16816(acc[mt][nt], afr[mt], bfr[nt]);
        }
        if (c + 1 < NCHUNK) __syncthreads();
    }

    const int er = lane >> 2;
    const int ec = (lane & 3) * 2;

    float bo[8], ga[8];
    #pragma unroll
    for (int mt = 0; mt < 4; ++mt) {
        const int r0 = wm + mt * 16 + er;
        bo[mt * 2] = bout[r0];        bo[mt * 2 + 1] = bout[r0 + 8];
        ga[mt * 2] = gam[r0];         ga[mt * 2 + 1] = gam[r0 + 8];
    }

    float cs[4][2], cq[4][2];
    #pragma unroll
    for (int nt = 0; nt < 4; ++nt)
        #pragma unroll
        for (int par = 0; par < 2; ++par) {
            float s = 0.f, q = 0.f;
            #pragma unroll
            for (int mt = 0; mt < 4; ++mt) {
                float v0 = acc[mt][nt][par]     + bo[mt * 2];
                float v1 = acc[mt][nt][par + 2] + bo[mt * 2 + 1];
                acc[mt][nt][par] = v0;
                acc[mt][nt][par + 2] = v1;
                s += v0 + v1;
                q += v0 * v0 + v1 * v1;
            }
            cs[nt][par] = s;
            cq[nt][par] = q;
        }
    #pragma unroll
    for (int off = 4; off < 32; off <<= 1)
        #pragma unroll
        for (int nt = 0; nt < 4; ++nt)
            #pragma unroll
            for (int par = 0; par < 2; ++par) {
                cs[nt][par] += __shfl_xor_sync(0xFFFFFFFFu, cs[nt][par], off);
                cq[nt][par] += __shfl_xor_sync(0xFFFFFFFFu, cq[nt][par], off);
            }

    float* red = (float*)smem;
    float2* lnp = (float2*)(smem + 2048);
    __syncthreads();
    if (er == 0) {
        const int wr = wid >> 1;
        #pragma unroll
        for (int nt = 0; nt < 4; ++nt)
            #pragma unroll
            for (int par = 0; par < 2; ++par) {
                const int col = wn + nt * 8 + ec + par;
                red[(wr * 64 + col) * 2]     = cs[nt][par];
                red[(wr * 64 + col) * 2 + 1] = cq[nt][par];
            }
    }
    __syncthreads();
    if (tid < 64) {
        float s = 0.f, q = 0.f;
        #pragma unroll
        for (int wr = 0; wr < 4; ++wr) {
            s += red[(wr * 64 + tid) * 2];
            q += red[(wr * 64 + tid) * 2 + 1];
        }
        const float mean = s * (1.f / 256.f);
        const float var = q * (1.f / 256.f) - mean * mean;
        lnp[tid] = make_float2(mean, rsqrtf(var + 1e-5f));
    }
    __syncthreads();

    #pragma unroll
    for (int mt = 0; mt < 4; ++mt)
        #pragma unroll
        for (int nt = 0; nt < 4; ++nt) {
            const float2 l0 = lnp[wn + nt * 8 + ec];
            const float2 l1 = lnp[wn + nt * 8 + ec + 1];
            float* p0 = Cb + (long)(wm + mt * 16 + er) * 4096 + wn + nt * 8 + ec;
            *reinterpret_cast<float2*>(p0) = make_float2(
                (acc[mt][nt][0] - l0.x) * l0.y * ga[mt * 2],
                (acc[mt][nt][1] - l1.x) * l1.y * ga[mt * 2]);
            *reinterpret_cast<float2*>(p0 + 8L * 4096) = make_float2(
                (acc[mt][nt][2] - l0.x) * l0.y * ga[mt * 2 + 1],
                (acc[mt][nt][3] - l1.x) * l1.y * ga[mt * 2 + 1]);
        }
}

// ---------------------------------------------------------------------------
__global__ __launch_bounds__(256) void conv_w_kernel(const float* __restrict__ w)
{
    const int m = blockIdx.x, c = threadIdx.x;
    g_W2[(long)m * KP + c] = __float2half(w[m * 256 + c]);
}

// ---------------------------------------------------------------------------
// x transpose: 32c x 128p tiles (round-13 layout), float4 loads (MLP 4).
// ---------------------------------------------------------------------------
__global__ __launch_bounds__(256) void transpose_x(const float* __restrict__ x)
{
    __shared__ float sm[32][129];
    const int b = blockIdx.z, c0 = blockIdx.y * 32, p0 = blockIdx.x * 128;
    const float* xb = x + ((long)b * 256 + c0) * 4096 + p0;
    const int tid = threadIdx.x;

    #pragma unroll
    for (int i = 0; i < 4; ++i) {
        const int u = tid + i * 256;        // 0..1023 float4 slots
        const int r = u >> 5;               // 0..31
        const int c4 = (u & 31) * 4;        // 0..124
        const float4 v = *reinterpret_cast<const float4*>(xb + (long)r * 4096 + c4);
        sm[r][c4] = v.x; sm[r][c4 + 1] = v.y; sm[r][c4 + 2] = v.z; sm[r][c4 + 3] = v.w;
    }
    __syncthreads();

    const int rr = tid >> 1, j0 = (tid & 1) * 16;
    __align__(16) __half hv[16];
    #pragma unroll
    for (int j = 0; j < 16; ++j) hv[j] = __float2half(sm[j0 + j][rr]);

    __half* ob = g_Bx + (((long)b * 4 + (c0 >> 6)) * NPIX + p0 + rr) * 64 + (c0 & 63) + j0;
    reinterpret_cast<uint4*>(ob)[0] = reinterpret_cast<const uint4*>(hv)[0];
    reinterpret_cast<uint4*>(ob)[1] = reinterpret_cast<const uint4*>(hv)[1];
}

// ---------------------------------------------------------------------------
// context via tensor cores: ctx[32,32] = ek[32,K] * v[32,K]^T per (b,h).
// grid (128 bh, 8 segs), 128 threads / 4 warps; swizzled 128B smem rows.
// ---------------------------------------------------------------------------
__global__ __launch_bounds__(128) void context_mma()
{
    __shared__ __half sK[3][DH][64];
    __shared__ __half sV[3][DH][64];
    __shared__ float red[4][DH][DH + 1];
    __shared__ float ki[DH];

    const int bh = blockIdx.x, seg = blockIdx.y;
    const int b = bh >> 3, h = bh & 7;
    const __half* kb = g_ek + ((long)b * 256 + h * DH) * 4096 + seg * 512;
    const __half* vb = g_v  + ((long)b * 256 + h * DH) * 4096 + seg * 512;

    const int tid = threadIdx.x;
    const int wid = tid >> 5;
    const int lane = tid & 31;

    if (tid < DH) {
        const float* pp = g_kpart + ((long)b * 256 + h * DH + tid) * 32;
        float s = 0.f;
        #pragma unroll
        for (int i = 0; i < 32; ++i) s += pp[i];
        ki[tid] = 1.f / s;
    }

    auto cp_stage = [&](int it) {
        const int s = it % 3;
        const int p0 = it * 64;
        const uint32_t aK = smem_u32(&sK[s][0][0]);
        const uint32_t aV = smem_u32(&sV[s][0][0]);
        #pragma unroll
        for (int i = 0; i < 2; ++i) {
            const int u = tid + i * 128;            // 0..255
            const int row = u >> 3;
            const uint32_t so = row * 128 + SW(row, (u & 7) * 16);
            cp16(aK + so, kb + (long)row * 4096 + p0 + (u & 7) * 8);
            cp16(aV + so, vb + (long)row * 4096 + p0 + (u & 7) * 8);
        }
        cp_commit();
    };

    float acc[2][4][4];
    #pragma unroll
    for (int i = 0; i < 2; ++i)
        #pragma unroll
        for (int j = 0; j < 4; ++j)
            #pragma unroll
            for (int k = 0; k < 4; ++k) acc[i][j][k] = 0.f;

    const int a_row = lane & 15;
    const int a_koff = (lane >> 4) * 16;
    const int swa = (a_row & 7) * 16;
    const int b_row = lane & 7;
    const int b_n8 = (lane >> 4) * 8;
    const int b_koff = ((lane >> 3) & 1) * 16;
    const int swb = b_row * 16;
    const int kwb = wid * 32;                       // warp k-slice byte offset

    cp_stage(0);
    cp_stage(1);

    for (int it = 0; it < 8; ++it) {
        const int s = it % 3;
        if (it < 7) cp_wait<1>(); else cp_wait<0>();
        __syncthreads();
        if (it + 2 < 8) cp_stage(it + 2);

        const uint32_t aK = smem_u32(&sK[s][0][0]);
        const uint32_t aV = smem_u32(&sV[s][0][0]);
        uint32_t afr[2][4], bfr[4][2];
        #pragma unroll
        for (int mt = 0; mt < 2; ++mt)
            ldsm_x4(afr[mt], aK + (mt * 16 + a_row) * 128 + ((kwb + a_koff) ^ swa));
        #pragma unroll
        for (int np = 0; np < 2; ++np) {
            uint32_t bq[4];
            ldsm_x4(bq, aV + (np * 16 + b_n8 + b_row) * 128 + ((kwb + b_koff) ^ swb));
            bfr[np * 2][0] = bq[0]; bfr[np * 2][1] = bq[1];
            bfr[np * 2 + 1][0] = bq[2]; bfr[np * 2 + 1][1] = bq[3];
        }
        #pragma unroll
        for (int mt = 0; mt < 2; ++mt)
            #pragma unroll
            for (int nt = 0; nt < 4; ++nt)
                mma16816(acc[mt][nt], afr[mt], bfr[nt]);
    }

    // ---- cross-warp reduce + ki scaling -------------------------------------
    const int er = lane >> 2;
    const int ec = (lane & 3) * 2;
    #pragma unroll
    for (int mt = 0; mt < 2; ++mt)
        #pragma unroll
        for (int nt = 0; nt < 4; ++nt) {
            const int d0 = mt * 16 + er;
            const int e0 = nt * 8 + ec;
            red[wid][d0][e0]     = acc[mt][nt][0];
            red[wid][d0][e0 + 1] = acc[mt][nt][1];
            red[wid][d0 + 8][e0]     = acc[mt][nt][2];
            red[wid][d0 + 8][e0 + 1] = acc[mt][nt][3];
        }
    __syncthreads();

    float* op = g_ctxp + ((long)bh * CSEG + seg) * (DH * DH);
    const float invn = 1.f / (float)NPIX;
    #pragma unroll
    for (int i = tid; i < DH * DH; i += 128) {
        const int d = i >> 5, e = i & 31;
        const float s = red[0][d][e] + red[1][d][e] + red[2][d][e] + red[3][d][e];
        op[i] = s * ki[d] * invn;
    }
}

// ---------------------------------------------------------------------------
// buildM -> single fp16 M in g_A2
// ---------------------------------------------------------------------------
__global__ __launch_bounds__(256) void buildM_kernel(const float* __restrict__ wout)
{
    const int bh = blockIdx.x;
    const int b = bh >> 3, h = bh & 7;

    __shared__ float cs[DH][DH + 1];
    const int tid = threadIdx.x;

    for (int i = tid; i < DH * DH; i += 256) {
        float s = 0.f;
        #pragma unroll
        for (int ch = 0; ch < CSEG; ++ch)
            s += g_ctxp[((long)bh * CSEG + ch) * (DH * DH) + i];
        cs[i >> 5][i & 31] = s;
    }
    __syncthreads();

    float w[DH];
    const float* wr = wout + (long)tid * 256 + h * DH;
    #pragma unroll
    for (int e = 0; e < DH; ++e) w[e] = wr[e];

    __align__(16) __half hi[DH];
    for (int d = 0; d < DH; ++d) {
        float s = 0.f;
        #pragma unroll
        for (int e = 0; e < DH; ++e) s += w[e] * cs[d][e];
        hi[d] = __float2half(s);
    }
    __half* ob = g_A2 + ((long)b * HID + tid) * KP + h * DH;
    #pragma unroll
    for (int i = 0; i < 4; ++i)
        reinterpret_cast<uint4*>(ob)[i] = reinterpret_cast<const uint4*>(hi)[i];
}

// ---------------------------------------------------------------------------
extern "C" void kernel_launch(void* const* d_in, const int* in_sizes, int n_in,
                              void* d_out, int out_size)
{
    (void)in_sizes; (void)n_in; (void)out_size;
    const float* x     = (const float*)d_in[0];
    const float* w_qkv = (const float*)d_in[1];
    const float* w_out = (const float*)d_in[2];
    const float* b_out = (const float*)d_in[3];
    const float* g     = (const float*)d_in[4];
    float* out = (float*)d_out;

    __half *p_W = nullptr, *p_Bx = nullptr, *p_Bq = nullptr, *p_A2 = nullptr;
    cudaGetSymbolAddress((void**)&p_W,   g_W2);
    cudaGetSymbolAddress((void**)&p_Bx,  g_Bx);
    cudaGetSymbolAddress((void**)&p_Bq,  g_Bq);
    cudaGetSymbolAddress((void**)&p_A2,  g_A2);

    cudaFuncSetAttribute(gemm_mma, cudaFuncAttributeMaxDynamicSharedMemorySize, SMEM1);
    cudaFuncSetAttribute(gemm_ln,  cudaFuncAttributeMaxDynamicSharedMemorySize, 2 * STG2);

    conv_w_kernel<<<QKV_ROWS, 256>>>(w_qkv);
    transpose_x<<<dim3(32, 8, BATCH), 256>>>(x);

    // QKV GEMM (single fp16, K=256, swizzled smem) + fused epilogues
    gemm_mma<<<dim3(6, 32, BATCH), 256, SMEM1>>>(p_W, p_Bx);

    // context partials via tensor cores (8 segments)
    context_mma<<<dim3(BATCH * HEADS, CSEG), 128>>>();

    // M fold -> single fp16
    buildM_kernel<<<BATCH * HEADS, 256>>>(w_out);

    // y GEMM (256x64 tiles, 256 thr, 2 CTAs/SM) + bias + LayerNorm -> d_out
    gemm_ln<<<dim3(64, 1, BATCH), 256, 2 * STG2>>>(p_A2, p_Bq, b_out, g, out);
}

// round 16
// speedup vs baseline: 1.1088x; 1.0613x over previous
#include <cuda_runtime.h>
#include <cuda_fp16.h>
#include <stdint.h>

#define BATCH   16
#define HID     256
#define HEADS   8
#define DH      32
#define NPIX    4096
#define QKV_ROWS 768
#define KP      256          // single-term fp16, K' = 256
#define NCHUNK  4            // K' / 64
#define CSEG    8            // context pixel segments

// ---------------- device scratch ------------------------------------------
__device__ __half g_ek[BATCH * 256 * NPIX];             // exp(k-4) fp16, 32 MB
__device__ __half g_v [BATCH * 256 * NPIX];             // v raw fp16, 32 MB
__device__ __half g_W2[QKV_ROWS * KP];                  // W fp16 [768,256]
__device__ __half g_Bx[BATCH * 4 * NPIX * 64];          // chunk-major x^T, 32 MB
__device__ __half g_Bq[BATCH * 4 * NPIX * 64];          // chunk-major softmaxed q^T, 32 MB
__device__ __half g_A2[BATCH * HID * KP];               // M fp16 [b,256,256]
__device__ float g_ctxp[BATCH * HEADS * CSEG * DH * DH]; // context partials
__device__ float g_kpart[BATCH * 256 * 16];             // k row sumexp partials per 256-col block

// ---------------- PTX helpers (base ISA only) ------------------------------
__device__ __forceinline__ uint32_t smem_u32(const void* p) {
    uint32_t a;
    asm("{ .reg .u64 t; cvta.to.shared.u64 t, %1; cvt.u32.u64 %0, t; }" : "=r"(a) : "l"(p));
    return a;
}
__device__ __forceinline__ void cp16(uint32_t saddr, const void* gaddr) {
    asm volatile("cp.async.cg.shared.global [%0], [%1], 16;" :: "r"(saddr), "l"(gaddr) : "memory");
}
__device__ __forceinline__ void cp_commit() {
    asm volatile("cp.async.commit_group;" ::: "memory");
}
template <int N>
__device__ __forceinline__ void cp_wait() {
    asm volatile("cp.async.wait_group %0;" :: "n"(N) : "memory");
}
__device__ __forceinline__ void ldsm_x4(uint32_t* r, uint32_t addr) {
    asm volatile("ldmatrix.sync.aligned.m8n8.x4.shared.b16 {%0,%1,%2,%3}, [%4];"
                 : "=r"(r[0]), "=r"(r[1]), "=r"(r[2]), "=r"(r[3]) : "r"(addr));
}
__device__ __forceinline__ void mma16816(float* c, const uint32_t* a, const uint32_t* b) {
    asm volatile(
        "mma.sync.aligned.m16n8k16.row.col.f32.f16.f16.f32 "
        "{%0,%1,%2,%3}, {%4,%5,%6,%7}, {%8,%9}, {%0,%1,%2,%3};"
        : "+f"(c[0]), "+f"(c[1]), "+f"(c[2]), "+f"(c[3])
        : "r"(a[0]), "r"(a[1]), "r"(a[2]), "r"(a[3]), "r"(b[0]), "r"(b[1]));
}
__device__ __forceinline__ void mma16816_h(uint32_t* c, const uint32_t* a, const uint32_t* b) {
    asm volatile(
        "mma.sync.aligned.m16n8k16.row.col.f16.f16.f16.f16 "
        "{%0,%1}, {%2,%3,%4,%5}, {%6,%7}, {%0,%1};"
        : "+r"(c[0]), "+r"(c[1])
        : "r"(a[0]), "r"(a[1]), "r"(a[2]), "r"(a[3]), "r"(b[0]), "r"(b[1]));
}

// 128B rows + XOR-16B swizzle: conflict-free ldmatrix across any 8-row phase
#define SW(row, col) (((uint32_t)(col)) ^ (((row) & 7) * 16))

#define LDS_B 128
#define A1_ST (128 * LDS_B)       // 16384
#define B1_ST (256 * LDS_B)       // 32768
#define STG1  (A1_ST + B1_ST)     // 49152 per stage
#define SMEM1 (2 * STG1)          // 98304, 2 stages

// ---------------------------------------------------------------------------
// GEMM1 + fused epilogues. 256 threads, 8 warps of 64x64 (f16 accum),
// CTA 128x256, BK=64, 2-stage cp.async.
// bx 0-1: q (softmax -> g_Bq fp16); 2-3: k (exp(k-4) fp16 + row sums);
// 4-5: v (raw fp16, direct half2 store).
// ---------------------------------------------------------------------------
__global__ __launch_bounds__(256, 2) void gemm_mma(
    const __half* __restrict__ A, const __half* __restrict__ B)
{
    extern __shared__ char smem[];
    const uint32_t sb = smem_u32(smem);
    const int tid = threadIdx.x;
    const int wid = tid >> 5;
    const int lane = tid & 31;
    const int bx = blockIdx.x, by = blockIdx.y, b = blockIdx.z;

    const char* Ab = (const char*)(A + (long)bx * 128 * KP);
    const char* Bb = (const char*)B + ((long)b * 4 * NPIX + (long)by * 256) * 128;

    const int wm = (wid >> 2) * 64;     // 2 m-groups
    const int wn = (wid & 3) * 64;      // 4 n-groups

    uint32_t hacc[4][8][2];
    #pragma unroll
    for (int i = 0; i < 4; ++i)
        #pragma unroll
        for (int j = 0; j < 8; ++j) { hacc[i][j][0] = 0u; hacc[i][j][1] = 0u; }

    const int r_ld = tid >> 3;              // 0..31
    const int c16 = (tid & 7) * 16;
    auto cp_chunk = [&](int c, int s) {
        const uint32_t as = sb + s * STG1;
        const uint32_t bs = as + A1_ST;
        const long akb = (long)c * 128;
        const long bko = (long)c * NPIX * 128;
        #pragma unroll
        for (int i = 0; i < 4; ++i) {           // A: 128 rows
            const int r = r_ld + i * 32;
            cp16(as + r * LDS_B + SW(r, c16), Ab + (long)r * (KP * 2) + akb + c16);
        }
        #pragma unroll
        for (int i = 0; i < 8; ++i) {           // B: 256 rows
            const int r = r_ld + i * 32;
            cp16(bs + r * LDS_B + SW(r, c16), Bb + bko + (long)r * 128 + c16);
        }
        cp_commit();
    };

    const int a_row = lane & 15;
    const int a_koff = (lane >> 4) * 16;
    const int swa = (a_row & 7) * 16;
    const int b_row = lane & 7;
    const int b_n8 = (lane >> 4) * 8;
    const int b_koff = ((lane >> 3) & 1) * 16;
    const int swb = b_row * 16;

    cp_chunk(0, 0);

    for (int c = 0; c < NCHUNK; ++c) {
        const int s = c & 1;
        if (c + 1 < NCHUNK) cp_chunk(c + 1, s ^ 1);
        if (c + 1 < NCHUNK) cp_wait<1>(); else cp_wait<0>();
        __syncthreads();

        const uint32_t as = sb + s * STG1;
        const uint32_t bs = as + A1_ST;
        #pragma unroll
        for (int ks = 0; ks < 4; ++ks) {
            uint32_t afr[4][4], bfr[8][2];
            #pragma unroll
            for (int mt = 0; mt < 4; ++mt)
                ldsm_x4(afr[mt], as + (wm + mt * 16 + a_row) * LDS_B + ((ks * 32 + a_koff) ^ swa));
            #pragma unroll
            for (int np = 0; np < 4; ++np) {
                uint32_t bq[4];
                ldsm_x4(bq, bs + (wn + np * 16 + b_n8 + b_row) * LDS_B + ((ks * 32 + b_koff) ^ swb));
                bfr[np * 2][0] = bq[0]; bfr[np * 2][1] = bq[1];
                bfr[np * 2 + 1][0] = bq[2]; bfr[np * 2 + 1][1] = bq[3];
            }
            #pragma unroll
            for (int mt = 0; mt < 4; ++mt)
                #pragma unroll
                for (int nt = 0; nt < 8; ++nt)
                    mma16816_h(hacc[mt][nt], afr[mt], bfr[nt]);
        }
        if (c + 1 < NCHUNK) __syncthreads();
    }

    const int er = lane >> 2;
    const int ec = (lane & 3) * 2;

    if (bx >= 4) {
        // ---- v: direct half2 store ------------------------------------------
        __half* Vb = g_v + ((long)b * 256 + (long)(bx - 4) * 128) * 4096 + by * 256;
        #pragma unroll
        for (int mt = 0; mt < 4; ++mt)
            #pragma unroll
            for (int nt = 0; nt < 8; ++nt) {
                const long r0 = wm + mt * 16 + er;
                const int c0 = wn + nt * 8 + ec;
                *reinterpret_cast<uint32_t*>(Vb + r0 * 4096 + c0) = hacc[mt][nt][0];
                *reinterpret_cast<uint32_t*>(Vb + (r0 + 8) * 4096 + c0) = hacc[mt][nt][1];
            }
        return;
    }

    if (bx >= 2) {
        // ---- k: exp(k-4) fp16 + row-sum partials ---------------------------
        __half* Ek = g_ek + ((long)b * 256 + (long)(bx - 2) * 128) * 4096 + by * 256;
        float rs[8];
        #pragma unroll
        for (int i = 0; i < 8; ++i) rs[i] = 0.f;
        #pragma unroll
        for (int mt = 0; mt < 4; ++mt)
            #pragma unroll
            for (int nt = 0; nt < 8; ++nt) {
                const float2 v0 = __half22float2(*reinterpret_cast<__half2*>(&hacc[mt][nt][0]));
                const float2 v1 = __half22float2(*reinterpret_cast<__half2*>(&hacc[mt][nt][1]));
                const float e0 = __expf(v0.x - 4.f);
                const float e1 = __expf(v0.y - 4.f);
                const float e2 = __expf(v1.x - 4.f);
                const float e3 = __expf(v1.y - 4.f);
                const long r0 = wm + mt * 16 + er;
                const int c0 = wn + nt * 8 + ec;
                *reinterpret_cast<__half2*>(Ek + r0 * 4096 + c0) = __floats2half2_rn(e0, e1);
                *reinterpret_cast<__half2*>(Ek + (r0 + 8) * 4096 + c0) = __floats2half2_rn(e2, e3);
                rs[mt * 2] += e0 + e1;
                rs[mt * 2 + 1] += e2 + e3;
            }
        #pragma unroll
        for (int off = 1; off < 4; off <<= 1)
            #pragma unroll
            for (int i = 0; i < 8; ++i)
                rs[i] += __shfl_xor_sync(0xFFFFFFFFu, rs[i], off);

        float* ssum = (float*)smem;   // [128 rows][4 n-quarters]
        __syncthreads();
        if ((lane & 3) == 0) {
            const int wq = wid & 3;
            #pragma unroll
            for (int mt = 0; mt < 4; ++mt)
                #pragma unroll
                for (int h2 = 0; h2 < 2; ++h2)
                    ssum[(wm + mt * 16 + er + h2 * 8) * 4 + wq] = rs[mt * 2 + h2];
        }
        __syncthreads();
        if (tid < 128)
            g_kpart[((long)b * 256 + (bx - 2) * 128 + tid) * 16 + by] =
                ssum[tid * 4] + ssum[tid * 4 + 1] + ssum[tid * 4 + 2] + ssum[tid * 4 + 3];
        return;
    }

    // ---- q: stage to fp16 smem, softmax over d, emit fp16 chunk-major ------
    __half* sfl = (__half*)smem;        // [128][264] halves = 67.6 KB
    __syncthreads();
    #pragma unroll
    for (int mt = 0; mt < 4; ++mt)
        #pragma unroll
        for (int nt = 0; nt < 8; ++nt) {
            const int r0 = wm + mt * 16 + er;
            const int c0 = wn + nt * 8 + ec;
            *reinterpret_cast<uint32_t*>(sfl + r0 * 264 + c0) = hacc[mt][nt][0];
            *reinterpret_cast<uint32_t*>(sfl + (r0 + 8) * 264 + c0) = hacc[mt][nt][1];
        }
    __syncthreads();

    #pragma unroll
    for (int t = tid; t < 1024; t += 256) {
        const int hb = t >> 8;          // head block 0..3
        const int col = t & 255;
        float v[DH];
        float m = -1e30f;
        #pragma unroll
        for (int d = 0; d < DH; ++d) {
            v[d] = __half2float(sfl[(hb * 32 + d) * 264 + col]);
            m = fmaxf(m, v[d]);
        }
        float s = 0.f;
        #pragma unroll
        for (int d = 0; d < DH; ++d) { v[d] = __expf(v[d] - m); s += v[d]; }
        const float inv = 0.1767766952966369f / s;
        __align__(16) __half o[DH];
        #pragma unroll
        for (int d = 0; d < DH; ++d) o[d] = __float2half(v[d] * inv);

        const int gh = bx * 4 + hb;
        const long gcol = (long)by * 256 + col;
        __half* ob = g_Bq + (((long)b * 4 + (gh >> 1)) * NPIX + gcol) * 64 + (gh & 1) * 32;
        #pragma unroll
        for (int i = 0; i < 4; ++i)
            reinterpret_cast<uint4*>(ob)[i] = reinterpret_cast<const uint4*>(o)[i];
    }
}

// ---------------------------------------------------------------------------
// GEMM2 + fused bias + LayerNorm. CTA tile 256x64, 256 threads, 2 CTAs/SM.
// fp32 accumulation (output path).
// ---------------------------------------------------------------------------
#define A2_ST (256 * LDS_B)       // 32768
#define B2_ST (64 * LDS_B)        // 8192
#define STG2  (A2_ST + B2_ST)     // 40960 per stage

__global__ __launch_bounds__(256, 2) void gemm_ln(
    const __half* __restrict__ A, const __half* __restrict__ B,
    const float* __restrict__ bout, const float* __restrict__ gam,
    float* __restrict__ out)
{
    extern __shared__ char smem[];
    const uint32_t sb = smem_u32(smem);
    const int tid = threadIdx.x;
    const int wid = tid >> 5;
    const int lane = tid & 31;
    const int b = blockIdx.z;
    const int n0 = blockIdx.x * 64;

    const char* Ab = (const char*)(A + (long)b * HID * KP);
    const char* Bb = (const char*)B + ((long)b * 4 * NPIX + n0) * 128;
    float* Cb = out + (long)b * HID * NPIX + n0;

    const int wm = (wid >> 1) * 64;
    const int wn = (wid & 1) * 32;

    float acc[4][4][4];
    #pragma unroll
    for (int i = 0; i < 4; ++i)
        #pragma unroll
        for (int j = 0; j < 4; ++j)
            #pragma unroll
            for (int k = 0; k < 4; ++k) acc[i][j][k] = 0.f;

    const int r_ld = tid >> 3;
    const int c16 = (tid & 7) * 16;
    auto cp_chunk = [&](int c, int s) {
        const uint32_t as = sb + s * STG2;
        const uint32_t bs = as + A2_ST;
        const long akb = (long)c * 128;
        const long bko = (long)c * NPIX * 128;
        #pragma unroll
        for (int i = 0; i < 8; ++i) {
            const int r = r_ld + i * 32;
            cp16(as + r * LDS_B + SW(r, c16), Ab + (long)r * (KP * 2) + akb + c16);
        }
        #pragma unroll
        for (int i = 0; i < 2; ++i) {
            const int r = r_ld + i * 32;
            cp16(bs + r * LDS_B + SW(r, c16), Bb + bko + (long)r * 128 + c16);
        }
        cp_commit();
    };

    const int a_row = lane & 15;
    const int a_koff = (lane >> 4) * 16;
    const int swa = (a_row & 7) * 16;
    const int b_row = lane & 7;
    const int b_n8 = (lane >> 4) * 8;
    const int b_koff = ((lane >> 3) & 1) * 16;
    const int swb = b_row * 16;

    cp_chunk(0, 0);

    #pragma unroll
    for (int c = 0; c < NCHUNK; ++c) {
        const int s = c & 1;
        if (c + 1 < NCHUNK) cp_chunk(c + 1, s ^ 1);
        if (c + 1 < NCHUNK) cp_wait<1>(); else cp_wait<0>();
        __syncthreads();

        const uint32_t as = sb + s * STG2;
        const uint32_t bs = as + A2_ST;
        #pragma unroll
        for (int ks = 0; ks < 4; ++ks) {
            uint32_t afr[4][4], bfr[4][2];
            #pragma unroll
            for (int mt = 0; mt < 4; ++mt)
                ldsm_x4(afr[mt], as + (wm + mt * 16 + a_row) * LDS_B + ((ks * 32 + a_koff) ^ swa));
            #pragma unroll
            for (int np = 0; np < 2; ++np) {
                uint32_t bq[4];
                ldsm_x4(bq, bs + (wn + np * 16 + b_n8 + b_row) * LDS_B + ((ks * 32 + b_koff) ^ swb));
                bfr[np * 2][0] = bq[0]; bfr[np * 2][1] = bq[1];
                bfr[np * 2 + 1][0] = bq[2]; bfr[np * 2 + 1][1] = bq[3];
            }
            #pragma unroll
            for (int mt = 0; mt < 4; ++mt)
                #pragma unroll
                for (int nt = 0; nt < 4; ++nt)
                    mma16816(acc[mt][nt], afr[mt], bfr[nt]);
        }
        if (c + 1 < NCHUNK) __syncthreads();
    }

    const int er = lane >> 2;
    const int ec = (lane & 3) * 2;

    float bo[8], ga[8];
    #pragma unroll
    for (int mt = 0; mt < 4; ++mt) {
        const int r0 = wm + mt * 16 + er;
        bo[mt * 2] = bout[r0];        bo[mt * 2 + 1] = bout[r0 + 8];
        ga[mt * 2] = gam[r0];         ga[mt * 2 + 1] = gam[r0 + 8];
    }

    float cs[4][2], cq[4][2];
    #pragma unroll
    for (int nt = 0; nt < 4; ++nt)
        #pragma unroll
        for (int par = 0; par < 2; ++par) {
            float s = 0.f, q = 0.f;
            #pragma unroll
            for (int mt = 0; mt < 4; ++mt) {
                float v0 = acc[mt][nt][par]     + bo[mt * 2];
                float v1 = acc[mt][nt][par + 2] + bo[mt * 2 + 1];
                acc[mt][nt][par] = v0;
                acc[mt][nt][par + 2] = v1;
                s += v0 + v1;
                q += v0 * v0 + v1 * v1;
            }
            cs[nt][par] = s;
            cq[nt][par] = q;
        }
    #pragma unroll
    for (int off = 4; off < 32; off <<= 1)
        #pragma unroll
        for (int nt = 0; nt < 4; ++nt)
            #pragma unroll
            for (int par = 0; par < 2; ++par) {
                cs[nt][par] += __shfl_xor_sync(0xFFFFFFFFu, cs[nt][par], off);
                cq[nt][par] += __shfl_xor_sync(0xFFFFFFFFu, cq[nt][par], off);
            }

    float* red = (float*)smem;
    float2* lnp = (float2*)(smem + 2048);
    __syncthreads();
    if (er == 0) {
        const int wr = wid >> 1;
        #pragma unroll
        for (int nt = 0; nt < 4; ++nt)
            #pragma unroll
            for (int par = 0; par < 2; ++par) {
                const int col = wn + nt * 8 + ec + par;
                red[(wr * 64 + col) * 2]     = cs[nt][par];
                red[(wr * 64 + col) * 2 + 1] = cq[nt][par];
            }
    }
    __syncthreads();
    if (tid < 64) {
        float s = 0.f, q = 0.f;
        #pragma unroll
        for (int wr = 0; wr < 4; ++wr) {
            s += red[(wr * 64 + tid) * 2];
            q += red[(wr * 64 + tid) * 2 + 1];
        }
        const float mean = s * (1.f / 256.f);
        const float var = q * (1.f / 256.f) - mean * mean;
        lnp[tid] = make_float2(mean, rsqrtf(var + 1e-5f));
    }
    __syncthreads();

    #pragma unroll
    for (int mt = 0; mt < 4; ++mt)
        #pragma unroll
        for (int nt = 0; nt < 4; ++nt) {
            const float2 l0 = lnp[wn + nt * 8 + ec];
            const float2 l1 = lnp[wn + nt * 8 + ec + 1];
            float* p0 = Cb + (long)(wm + mt * 16 + er) * 4096 + wn + nt * 8 + ec;
            *reinterpret_cast<float2*>(p0) = make_float2(
                (acc[mt][nt][0] - l0.x) * l0.y * ga[mt * 2],
                (acc[mt][nt][1] - l1.x) * l1.y * ga[mt * 2]);
            *reinterpret_cast<float2*>(p0 + 8L * 4096) = make_float2(
                (acc[mt][nt][2] - l0.x) * l0.y * ga[mt * 2 + 1],
                (acc[mt][nt][3] - l1.x) * l1.y * ga[mt * 2 + 1]);
        }
}

// ---------------------------------------------------------------------------
__global__ __launch_bounds__(256) void conv_w_kernel(const float* __restrict__ w)
{
    const int m = blockIdx.x, c = threadIdx.x;
    g_W2[(long)m * KP + c] = __float2half(w[m * 256 + c]);
}

// ---------------------------------------------------------------------------
// x transpose: 32c x 128p tiles, float4 loads.
// ---------------------------------------------------------------------------
__global__ __launch_bounds__(256) void transpose_x(const float* __restrict__ x)
{
    __shared__ float sm[32][129];
    const int b = blockIdx.z, c0 = blockIdx.y * 32, p0 = blockIdx.x * 128;
    const float* xb = x + ((long)b * 256 + c0) * 4096 + p0;
    const int tid = threadIdx.x;

    #pragma unroll
    for (int i = 0; i < 4; ++i) {
        const int u = tid + i * 256;
        const int r = u >> 5;
        const int c4 = (u & 31) * 4;
        const float4 v = *reinterpret_cast<const float4*>(xb + (long)r * 4096 + c4);
        sm[r][c4] = v.x; sm[r][c4 + 1] = v.y; sm[r][c4 + 2] = v.z; sm[r][c4 + 3] = v.w;
    }
    __syncthreads();

    const int rr = tid >> 1, j0 = (tid & 1) * 16;
    __align__(16) __half hv[16];
    #pragma unroll
    for (int j = 0; j < 16; ++j) hv[j] = __float2half(sm[j0 + j][rr]);

    __half* ob = g_Bx + (((long)b * 4 + (c0 >> 6)) * NPIX + p0 + rr) * 64 + (c0 & 63) + j0;
    reinterpret_cast<uint4*>(ob)[0] = reinterpret_cast<const uint4*>(hv)[0];
    reinterpret_cast<uint4*>(ob)[1] = reinterpret_cast<const uint4*>(hv)[1];
}

// ---------------------------------------------------------------------------
// context via tensor cores: ctx[32,32] = ek[32,K] * v[32,K]^T per (b,h).
// grid (128 bh, 8 segs), 128 threads / 4 warps; swizzled 128B smem rows.
// ---------------------------------------------------------------------------
__global__ __launch_bounds__(128) void context_mma()
{
    __shared__ __half sK[3][DH][64];
    __shared__ __half sV[3][DH][64];
    __shared__ float red[4][DH][DH + 1];
    __shared__ float ki[DH];

    const int bh = blockIdx.x, seg = blockIdx.y;
    const int b = bh >> 3, h = bh & 7;
    const __half* kb = g_ek + ((long)b * 256 + h * DH) * 4096 + seg * 512;
    const __half* vb = g_v  + ((long)b * 256 + h * DH) * 4096 + seg * 512;

    const int tid = threadIdx.x;
    const int wid = tid >> 5;
    const int lane = tid & 31;

    if (tid < DH) {
        const float* pp = g_kpart + ((long)b * 256 + h * DH + tid) * 16;
        float s = 0.f;
        #pragma unroll
        for (int i = 0; i < 16; ++i) s += pp[i];
        ki[tid] = 1.f / s;
    }

    auto cp_stage = [&](int it) {
        const int s = it % 3;
        const int p0 = it * 64;
        const uint32_t aK = smem_u32(&sK[s][0][0]);
        const uint32_t aV = smem_u32(&sV[s][0][0]);
        #pragma unroll
        for (int i = 0; i < 2; ++i) {
            const int u = tid + i * 128;
            const int row = u >> 3;
            const uint32_t so = row * 128 + SW(row, (u & 7) * 16);
            cp16(aK + so, kb + (long)row * 4096 + p0 + (u & 7) * 8);
            cp16(aV + so, vb + (long)row * 4096 + p0 + (u & 7) * 8);
        }
        cp_commit();
    };

    float acc[2][4][4];
    #pragma unroll
    for (int i = 0; i < 2; ++i)
        #pragma unroll
        for (int j = 0; j < 4; ++j)
            #pragma unroll
            for (int k = 0; k < 4; ++k) acc[i][j][k] = 0.f;

    const int a_row = lane & 15;
    const int a_koff = (lane >> 4) * 16;
    const int swa = (a_row & 7) * 16;
    const int b_row = lane & 7;
    const int b_n8 = (lane >> 4) * 8;
    const int b_koff = ((lane >> 3) & 1) * 16;
    const int swb = b_row * 16;
    const int kwb = wid * 32;

    cp_stage(0);
    cp_stage(1);

    for (int it = 0; it < 8; ++it) {
        const int s = it % 3;
        if (it < 7) cp_wait<1>(); else cp_wait<0>();
        __syncthreads();
        if (it + 2 < 8) cp_stage(it + 2);

        const uint32_t aK = smem_u32(&sK[s][0][0]);
        const uint32_t aV = smem_u32(&sV[s][0][0]);
        uint32_t afr[2][4], bfr[4][2];
        #pragma unroll
        for (int mt = 0; mt < 2; ++mt)
            ldsm_x4(afr[mt], aK + (mt * 16 + a_row) * 128 + ((kwb + a_koff) ^ swa));
        #pragma unroll
        for (int np = 0; np < 2; ++np) {
            uint32_t bq[4];
            ldsm_x4(bq, aV + (np * 16 + b_n8 + b_row) * 128 + ((kwb + b_koff) ^ swb));
            bfr[np * 2][0] = bq[0]; bfr[np * 2][1] = bq[1];
            bfr[np * 2 + 1][0] = bq[2]; bfr[np * 2 + 1][1] = bq[3];
        }
        #pragma unroll
        for (int mt = 0; mt < 2; ++mt)
            #pragma unroll
            for (int nt = 0; nt < 4; ++nt)
                mma16816(acc[mt][nt], afr[mt], bfr[nt]);
    }

    const int er = lane >> 2;
    const int ec = (lane & 3) * 2;
    #pragma unroll
    for (int mt = 0; mt < 2; ++mt)
        #pragma unroll
        for (int nt = 0; nt < 4; ++nt) {
            const int d0 = mt * 16 + er;
            const int e0 = nt * 8 + ec;
            red[wid][d0][e0]     = acc[mt][nt][0];
            red[wid][d0][e0 + 1] = acc[mt][nt][1];
            red[wid][d0 + 8][e0]     = acc[mt][nt][2];
            red[wid][d0 + 8][e0 + 1] = acc[mt][nt][3];
        }
    __syncthreads();

    float* op = g_ctxp + ((long)bh * CSEG + seg) * (DH * DH);
    const float invn = 1.f / (float)NPIX;
    #pragma unroll
    for (int i = tid; i < DH * DH; i += 128) {
        const int d = i >> 5, e = i & 31;
        const float s = red[0][d][e] + red[1][d][e] + red[2][d][e] + red[3][d][e];
        op[i] = s * ki[d] * invn;
    }
}

// ---------------------------------------------------------------------------
// buildM -> single fp16 M in g_A2
// ---------------------------------------------------------------------------
__global__ __launch_bounds__(256) void buildM_kernel(const float* __restrict__ wout)
{
    const int bh = blockIdx.x;
    const int b = bh >> 3, h = bh & 7;

    __shared__ float cs[DH][DH + 1];
    const int tid = threadIdx.x;

    for (int i = tid; i < DH * DH; i += 256) {
        float s = 0.f;
        #pragma unroll
        for (int ch = 0; ch < CSEG; ++ch)
            s += g_ctxp[((long)bh * CSEG + ch) * (DH * DH) + i];
        cs[i >> 5][i & 31] = s;
    }
    __syncthreads();

    float w[DH];
    const float* wr = wout + (long)tid * 256 + h * DH;
    #pragma unroll
    for (int e = 0; e < DH; ++e) w[e] = wr[e];

    __align__(16) __half hi[DH];
    for (int d = 0; d < DH; ++d) {
        float s = 0.f;
        #pragma unroll
        for (int e = 0; e < DH; ++e) s += w[e] * cs[d][e];
        hi[d] = __float2half(s);
    }
    __half* ob = g_A2 + ((long)b * HID + tid) * KP + h * DH;
    #pragma unroll
    for (int i = 0; i < 4; ++i)
        reinterpret_cast<uint4*>(ob)[i] = reinterpret_cast<const uint4*>(hi)[i];
}

// ---------------------------------------------------------------------------
extern "C" void kernel_launch(void* const* d_in, const int* in_sizes, int n_in,
                              void* d_out, int out_size)
{
    (void)in_sizes; (void)n_in; (void)out_size;
    const float* x     = (const float*)d_in[0];
    const float* w_qkv = (const float*)d_in[1];
    const float* w_out = (const float*)d_in[2];
    const float* b_out = (const float*)d_in[3];
    const float* g     = (const float*)d_in[4];
    float* out = (float*)d_out;

    __half *p_W = nullptr, *p_Bx = nullptr, *p_Bq = nullptr, *p_A2 = nullptr;
    cudaGetSymbolAddress((void**)&p_W,   g_W2);
    cudaGetSymbolAddress((void**)&p_Bx,  g_Bx);
    cudaGetSymbolAddress((void**)&p_Bq,  g_Bq);
    cudaGetSymbolAddress((void**)&p_A2,  g_A2);

    cudaFuncSetAttribute(gemm_mma, cudaFuncAttributeMaxDynamicSharedMemorySize, SMEM1);
    cudaFuncSetAttribute(gemm_ln,  cudaFuncAttributeMaxDynamicSharedMemorySize, 2 * STG2);

    conv_w_kernel<<<QKV_ROWS, 256>>>(w_qkv);
    transpose_x<<<dim3(32, 8, BATCH), 256>>>(x);

    // QKV GEMM (f16 accum, 128x256 tiles, 64x64 warps) + fused epilogues
    gemm_mma<<<dim3(6, 16, BATCH), 256, SMEM1>>>(p_W, p_Bx);

    // context partials via tensor cores (8 segments)
    context_mma<<<dim3(BATCH * HEADS, CSEG), 128>>>();

    // M fold -> single fp16
    buildM_kernel<<<BATCH * HEADS, 256>>>(w_out);

    // y GEMM (256x64 tiles, 256 thr, 2 CTAs/SM, fp32 accum) + bias + LN
    gemm_ln<<<dim3(64, 1, BATCH), 256, 2 * STG2>>>(p_A2, p_Bq, b_out, g, out);
}